// round 7
// baseline (speedup 1.0000x reference)
#include <cuda_runtime.h>
#include <math.h>
#include <cstdint>

#define NROWS 8192
#define DDIM  128
#define NTILE (NROWS / 128)
#define NTRI  (NTILE * (NTILE + 1) / 2)   // 2080

// ---------------- scratch ----------------------------------------------------
__device__ float g_eT[DDIM * NROWS];      // normalized fp32, transposed [d][i]
__device__ char  g_q[NROWS * DDIM];       // int8 quantized normalized rows [i][d]
__device__ float g_s[NROWS];              // per-row scale * sqrt(log2e)
__device__ float g_denom[NROWS];
__device__ float g_M[2][DDIM];
__device__ int   g_cnt[2];
__device__ float g_acc[2];
__device__ int   g_lblstride;
__device__ int   g_done;

// ---------------- helpers ----------------------------------------------------
__device__ __forceinline__ uint32_t smem_u32(const void* p) {
    uint32_t a;
    asm("{ .reg .u64 t; cvta.to.shared.u64 t, %1; cvt.u32.u64 %0, t; }" : "=r"(a) : "l"(p));
    return a;
}
__device__ __forceinline__ float ex2f(float x) {
    float r;
    asm("ex2.approx.ftz.f32 %0, %1;" : "=f"(r) : "f"(x));
    return r;
}
__device__ __forceinline__ void ldsm_x4(uint32_t a, uint32_t& r0, uint32_t& r1,
                                        uint32_t& r2, uint32_t& r3) {
    asm volatile("ldmatrix.sync.aligned.m8n8.x4.shared.b16 {%0,%1,%2,%3}, [%4];"
                 : "=r"(r0), "=r"(r1), "=r"(r2), "=r"(r3) : "r"(a));
}
__device__ __forceinline__ void mma16832s8(int* c, uint32_t a0, uint32_t a1,
                                           uint32_t a2, uint32_t a3,
                                           uint32_t b0, uint32_t b1) {
    asm volatile(
        "mma.sync.aligned.m16n8k32.row.col.s32.s8.s8.s32 "
        "{%0,%1,%2,%3}, {%4,%5,%6,%7}, {%8,%9}, {%0,%1,%2,%3};"
        : "+r"(c[0]), "+r"(c[1]), "+r"(c[2]), "+r"(c[3])
        : "r"(a0), "r"(a1), "r"(a2), "r"(a3), "r"(b0), "r"(b1));
}
__device__ __forceinline__ int get_label(const int* l32, int i) { return l32[i * g_lblstride]; }

// ---------------- K_init: zero + label-dtype sniff --------------------------
__global__ void k_init(const int* __restrict__ l32) {
    if (blockIdx.x < 32) {
        int t = blockIdx.x * 256 + threadIdx.x;
        if (t < NROWS) g_denom[t] = 0.0f;
        if (t < 2 * DDIM) ((float*)g_M)[t] = 0.0f;
        if (t < 2) { g_cnt[t] = 0; g_acc[t] = 0.0f; }
        if (t == 0) g_done = 0;
    } else {
        int t = threadIdx.x, nz = 0;
        for (int i = t; i < NROWS / 2; i += 256) nz |= l32[2 * i + 1];
        __shared__ int s;
        if (t == 0) s = 0;
        __syncthreads();
        if (nz) atomicOr(&s, 1);
        __syncthreads();
        if (t == 0) g_lblstride = s ? 1 : 2;
    }
}

// ---------------- K1: normalize + int8 quantize + fused class sums ---------
// one warp per row; block = 8 rows; class sums staged in smem then atomics.
__global__ void k_normalize(const float* __restrict__ emb, const int* __restrict__ l32) {
    const float SQRT_LOG2E = 1.2011224087864498f;
    int tid = threadIdx.x;
    int warp = tid >> 5, lane = tid & 31;
    int row = blockIdx.x * 8 + warp;

    __shared__ float sM[2 * DDIM];
    __shared__ int   scnt[2];
    sM[tid] = 0.0f;
    if (tid < 2) scnt[tid] = 0;
    __syncthreads();

    float4 v = ((const float4*)(emb + (size_t)row * DDIM))[lane];
    float ss = v.x * v.x + v.y * v.y + v.z * v.z + v.w * v.w;
    float mx = fmaxf(fmaxf(fabsf(v.x), fabsf(v.y)), fmaxf(fabsf(v.z), fabsf(v.w)));
    #pragma unroll
    for (int o = 16; o; o >>= 1) {
        ss += __shfl_xor_sync(0xffffffffu, ss, o);
        mx = fmaxf(mx, __shfl_xor_sync(0xffffffffu, mx, o));
    }
    float r = rsqrtf(ss);
    float m = mx * r;                    // max |normalized element|
    float qs = 127.0f / m;
    int d = lane * 4;
    float e0 = v.x * r, e1 = v.y * r, e2 = v.z * r, e3 = v.w * r;
    g_eT[(d + 0) * NROWS + row] = e0;
    g_eT[(d + 1) * NROWS + row] = e1;
    g_eT[(d + 2) * NROWS + row] = e2;
    g_eT[(d + 3) * NROWS + row] = e3;
    char4 q = make_char4((char)__float2int_rn(e0 * qs), (char)__float2int_rn(e1 * qs),
                         (char)__float2int_rn(e2 * qs), (char)__float2int_rn(e3 * qs));
    *(char4*)&g_q[(size_t)row * DDIM + d] = q;
    int c = (get_label(l32, row) == 0) ? 0 : 1;
    if (lane == 0) {
        g_s[row] = (m / 127.0f) * SQRT_LOG2E;
        atomicAdd(&scnt[c], 1);
    }
    float* sMc = &sM[c * DDIM + d];
    atomicAdd(&sMc[0], e0);
    atomicAdd(&sMc[1], e1);
    atomicAdd(&sMc[2], e2);
    atomicAdd(&sMc[3], e3);
    __syncthreads();
    atomicAdd(&((float*)g_M)[tid], sM[tid]);
    if (tid < 2) atomicAdd(&g_cnt[tid], scnt[tid]);
}

// ---------------- K3: int8 MMA sim tiles, upper triangle --------------------
// CTA = 128x128 tile; 8 warps as 2(m) x 4(n); warp tile 64x32; s32 acc.
// kk: K=128 as 4 steps of k32. SMEM rows 128B, chunk c at (c ^ (r&7)).
__global__ void __launch_bounds__(256, 2) k_sim() {
    int idx = blockIdx.x;
    int bj = (int)((sqrtf(8.0f * (float)idx + 1.0f) - 1.0f) * 0.5f);
    while ((bj + 1) * (bj + 2) / 2 <= idx) bj++;
    while (bj * (bj + 1) / 2 > idx) bj--;
    int bi = idx - bj * (bj + 1) / 2;

    __shared__ __align__(16) char smA[128 * 128];
    __shared__ __align__(16) char smB[128 * 128];
    __shared__ float sA[128], sB[128];
    __shared__ float red[128], redc[128];

    uint32_t sbA = smem_u32(smA), sbB = smem_u32(smB);
    int tid = threadIdx.x;
    int wid = tid >> 5, lane = tid & 31;
    int i0 = bi * 128, j0 = bj * 128;
    bool diag = (bi == bj);

    if (tid < 128) {
        red[tid] = 0.0f; redc[tid] = 0.0f;
        sA[tid] = g_s[i0 + tid];
        sB[tid] = g_s[j0 + tid];
    }
    // tile loads: 1024 16B-chunks each, 4 per thread
    #pragma unroll
    for (int c = 0; c < 4; c++) {
        int flat = c * 256 + tid;
        int row = flat >> 3, ch = flat & 7;
        uint32_t off = (uint32_t)(row * 128 + ((ch ^ (row & 7)) << 4));
        *(uint4*)(smA + off) = ((const uint4*)&g_q[(size_t)(i0 + row) * DDIM])[ch];
        *(uint4*)(smB + off) = ((const uint4*)&g_q[(size_t)(j0 + row) * DDIM])[ch];
    }
    __syncthreads();

    int m_off = (wid >> 2) * 64;       // 0 or 64
    int n_off = (wid & 3) * 32;        // 0,32,64,96

    int acc[4][4][4];
    #pragma unroll
    for (int mt = 0; mt < 4; mt++)
        #pragma unroll
        for (int nt = 0; nt < 4; nt++)
            #pragma unroll
            for (int e = 0; e < 4; e++) acc[mt][nt][e] = 0;

    uint32_t rowA = (uint32_t)(m_off + (lane & 15));
    uint32_t chA  = (uint32_t)(lane >> 4);
    uint32_t rowB = (uint32_t)(n_off + (lane & 7) + ((lane >> 4) << 3));
    uint32_t chB  = (uint32_t)((lane >> 3) & 1);

    #pragma unroll
    for (int kk = 0; kk < 4; kk++) {
        uint32_t a[4][4];
        #pragma unroll
        for (int mt = 0; mt < 4; mt++) {
            uint32_t r = rowA + mt * 16;
            uint32_t ch = (uint32_t)(kk * 2) + chA;
            ldsm_x4(sbA + r * 128 + ((ch ^ (r & 7)) << 4),
                    a[mt][0], a[mt][1], a[mt][2], a[mt][3]);
        }
        uint32_t b[4][2];
        #pragma unroll
        for (int p = 0; p < 2; p++) {
            uint32_t r = rowB + (uint32_t)(p * 16);
            uint32_t ch = (uint32_t)(kk * 2) + chB;
            ldsm_x4(sbB + r * 128 + ((ch ^ (r & 7)) << 4),
                    b[2 * p][0], b[2 * p][1], b[2 * p + 1][0], b[2 * p + 1][1]);
        }
        #pragma unroll
        for (int mt = 0; mt < 4; mt++)
            #pragma unroll
            for (int nt = 0; nt < 4; nt++)
                mma16832s8(acc[mt][nt], a[mt][0], a[mt][1], a[mt][2], a[mt][3],
                           b[nt][0], b[nt][1]);
    }

    // ---- epilogue: e = exp2(acc * s_i * s_j), row sums + col sums ----
    int lrow = lane >> 2;
    int lcol = (lane & 3) * 2;
    float2 cs[4];
    #pragma unroll
    for (int nt = 0; nt < 4; nt++)
        cs[nt] = *(float2*)&sB[n_off + nt * 8 + lcol];

    float colacc[4][2];
    #pragma unroll
    for (int nt = 0; nt < 4; nt++) { colacc[nt][0] = 0.0f; colacc[nt][1] = 0.0f; }

    #pragma unroll
    for (int mt = 0; mt < 4; mt++) {
        int grow0 = i0 + m_off + mt * 16 + lrow;
        float rs0 = sA[m_off + mt * 16 + lrow];
        float rs1 = sA[m_off + mt * 16 + lrow + 8];
        float s0 = 0.0f, s1 = 0.0f;
        #pragma unroll
        for (int nt = 0; nt < 4; nt++) {
            int gcol = j0 + n_off + nt * 8 + lcol;
            float e0 = ex2f((float)acc[mt][nt][0] * (rs0 * cs[nt].x));
            float e1 = ex2f((float)acc[mt][nt][1] * (rs0 * cs[nt].y));
            float e2 = ex2f((float)acc[mt][nt][2] * (rs1 * cs[nt].x));
            float e3 = ex2f((float)acc[mt][nt][3] * (rs1 * cs[nt].y));
            if (diag) {
                if (gcol     == grow0)     e0 = 0.0f;
                if (gcol + 1 == grow0)     e1 = 0.0f;
                if (gcol     == grow0 + 8) e2 = 0.0f;
                if (gcol + 1 == grow0 + 8) e3 = 0.0f;
            }
            s0 += e0 + e1;
            s1 += e2 + e3;
            colacc[nt][0] += e0 + e2;
            colacc[nt][1] += e1 + e3;
        }
        s0 += __shfl_xor_sync(0xffffffffu, s0, 1);
        s0 += __shfl_xor_sync(0xffffffffu, s0, 2);
        s1 += __shfl_xor_sync(0xffffffffu, s1, 1);
        s1 += __shfl_xor_sync(0xffffffffu, s1, 2);
        if ((lane & 3) == 0) {
            atomicAdd(&red[m_off + mt * 16 + lrow], s0);
            atomicAdd(&red[m_off + mt * 16 + lrow + 8], s1);
        }
    }

    if (!diag) {
        #pragma unroll
        for (int nt = 0; nt < 4; nt++) {
            #pragma unroll
            for (int h = 0; h < 2; h++) {
                float c = colacc[nt][h];
                c += __shfl_xor_sync(0xffffffffu, c, 4);
                c += __shfl_xor_sync(0xffffffffu, c, 8);
                c += __shfl_xor_sync(0xffffffffu, c, 16);
                if (lane < 4)
                    atomicAdd(&redc[n_off + nt * 8 + (lane & 3) * 2 + h], c);
            }
        }
    }

    __syncthreads();
    if (tid < 128) {
        atomicAdd(&g_denom[i0 + tid], red[tid]);
        if (!diag) atomicAdd(&g_denom[j0 + tid], redc[tid]);
    }
}

// ---------------- K4: per-row loss + per-class reduce + fused final ---------
__global__ void k_loss(const int* __restrict__ l32, float* __restrict__ out) {
    int i = blockIdx.x * 256 + threadIdx.x;
    int t = threadIdx.x;
    int c = (get_label(l32, i) == 0) ? 0 : 1;
    const float* Mc = g_M[c];
    float pos = 0.0f;
    #pragma unroll 16
    for (int d = 0; d < DDIM; d++)
        pos += g_eT[d * NROWS + i] * Mc[d];
    pos -= 1.0f;
    float cntm1 = (float)(g_cnt[c] - 1);
    float li = -(pos - cntm1 * logf(g_denom[i]));

    __shared__ float sh0[256], sh1[256];
    sh0[t] = (c == 0) ? li : 0.0f;
    sh1[t] = (c == 0) ? 0.0f : li;
    __syncthreads();
    for (int st = 128; st; st >>= 1) {
        if (t < st) { sh0[t] += sh0[t + st]; sh1[t] += sh1[t + st]; }
        __syncthreads();
    }
    __shared__ int ticket;
    if (t == 0) {
        atomicAdd(&g_acc[0], sh0[0]);
        atomicAdd(&g_acc[1], sh1[0]);
        __threadfence();
        ticket = atomicAdd(&g_done, 1);
    }
    __syncthreads();
    if (t == 0 && ticket == gridDim.x - 1) {
        out[0] = g_acc[0] / (float)g_cnt[0] + g_acc[1];
    }
}

// ---------------- launch -----------------------------------------------------
extern "C" void kernel_launch(void* const* d_in, const int* in_sizes, int n_in,
                              void* d_out, int out_size) {
    const float* emb = (const float*)d_in[0];
    const int*   l32 = (const int*)d_in[1];
    float*       out = (float*)d_out;

    k_init<<<33, 256>>>(l32);
    k_normalize<<<NROWS / 8, 256>>>(emb, l32);
    k_sim<<<NTRI, 256>>>();
    k_loss<<<NROWS / 256, 256>>>(l32, out);
}

// round 8
// speedup vs baseline: 1.0919x; 1.0919x over previous
#include <cuda_runtime.h>
#include <math.h>
#include <cstdint>

#define NROWS 8192
#define DDIM  128
#define NTILE (NROWS / 128)
#define NTRI  (NTILE * (NTILE + 1) / 2)   // 2080

// ---------------- scratch ----------------------------------------------------
__device__ char  g_q[NROWS * DDIM];       // int8 quantized normalized rows [i][d]
__device__ float g_s[NROWS];              // per-row scale * sqrt(log2e)
__device__ float g_denom[NROWS];
__device__ float g_M[2][DDIM];            // per-class sums of normalized rows
__device__ int   g_cnt[2];
__device__ float g_L[2];                  // per-class sums of log(denom)
__device__ int   g_lblstride;
__device__ int   g_done;

// ---------------- helpers ----------------------------------------------------
__device__ __forceinline__ uint32_t smem_u32(const void* p) {
    uint32_t a;
    asm("{ .reg .u64 t; cvta.to.shared.u64 t, %1; cvt.u32.u64 %0, t; }" : "=r"(a) : "l"(p));
    return a;
}
__device__ __forceinline__ float ex2f(float x) {
    float r;
    asm("ex2.approx.ftz.f32 %0, %1;" : "=f"(r) : "f"(x));
    return r;
}
__device__ __forceinline__ void ldsm_x4(uint32_t a, uint32_t& r0, uint32_t& r1,
                                        uint32_t& r2, uint32_t& r3) {
    asm volatile("ldmatrix.sync.aligned.m8n8.x4.shared.b16 {%0,%1,%2,%3}, [%4];"
                 : "=r"(r0), "=r"(r1), "=r"(r2), "=r"(r3) : "r"(a));
}
__device__ __forceinline__ void mma16832s8(int* c, uint32_t a0, uint32_t a1,
                                           uint32_t a2, uint32_t a3,
                                           uint32_t b0, uint32_t b1) {
    asm volatile(
        "mma.sync.aligned.m16n8k32.row.col.s32.s8.s8.s32 "
        "{%0,%1,%2,%3}, {%4,%5,%6,%7}, {%8,%9}, {%0,%1,%2,%3};"
        : "+r"(c[0]), "+r"(c[1]), "+r"(c[2]), "+r"(c[3])
        : "r"(a0), "r"(a1), "r"(a2), "r"(a3), "r"(b0), "r"(b1));
}
__device__ __forceinline__ int get_label(const int* l32, int i) { return l32[i * g_lblstride]; }

// ---------------- K_init: zero + label-dtype sniff --------------------------
__global__ void k_init(const int* __restrict__ l32) {
    if (blockIdx.x < 32) {
        int t = blockIdx.x * 256 + threadIdx.x;
        if (t < NROWS) g_denom[t] = 0.0f;
        if (t < 2 * DDIM) ((float*)g_M)[t] = 0.0f;
        if (t < 2) { g_cnt[t] = 0; g_L[t] = 0.0f; }
        if (t == 0) g_done = 0;
    } else {
        int t = threadIdx.x, nz = 0;
        for (int i = t; i < NROWS / 2; i += 256) nz |= l32[2 * i + 1];
        __shared__ int s;
        if (t == 0) s = 0;
        __syncthreads();
        if (nz) atomicOr(&s, 1);
        __syncthreads();
        if (t == 0) g_lblstride = s ? 1 : 2;
    }
}

// ---------------- K1: normalize + int8 quantize + fused class sums ---------
// one warp per row; block = 8 rows; class sums staged in smem then atomics.
// NOTE: no fp32 matrix written anywhere — only 1MB of int8 + scales.
__global__ void k_normalize(const float* __restrict__ emb, const int* __restrict__ l32) {
    const float SQRT_LOG2E = 1.2011224087864498f;
    int tid = threadIdx.x;
    int warp = tid >> 5, lane = tid & 31;
    int row = blockIdx.x * 8 + warp;

    __shared__ float sM[2 * DDIM];
    __shared__ int   scnt[2];
    sM[tid] = 0.0f;
    if (tid < 2) scnt[tid] = 0;
    __syncthreads();

    float4 v = ((const float4*)(emb + (size_t)row * DDIM))[lane];
    float ss = v.x * v.x + v.y * v.y + v.z * v.z + v.w * v.w;
    float mx = fmaxf(fmaxf(fabsf(v.x), fabsf(v.y)), fmaxf(fabsf(v.z), fabsf(v.w)));
    #pragma unroll
    for (int o = 16; o; o >>= 1) {
        ss += __shfl_xor_sync(0xffffffffu, ss, o);
        mx = fmaxf(mx, __shfl_xor_sync(0xffffffffu, mx, o));
    }
    float r = rsqrtf(ss);
    float m = mx * r;                    // max |normalized element|
    float qs = 127.0f / m;
    int d = lane * 4;
    float e0 = v.x * r, e1 = v.y * r, e2 = v.z * r, e3 = v.w * r;
    char4 q = make_char4((char)__float2int_rn(e0 * qs), (char)__float2int_rn(e1 * qs),
                         (char)__float2int_rn(e2 * qs), (char)__float2int_rn(e3 * qs));
    *(char4*)&g_q[(size_t)row * DDIM + d] = q;
    int c = (get_label(l32, row) == 0) ? 0 : 1;
    if (lane == 0) {
        g_s[row] = (m / 127.0f) * SQRT_LOG2E;
        atomicAdd(&scnt[c], 1);
    }
    float* sMc = &sM[c * DDIM + d];
    atomicAdd(&sMc[0], e0);
    atomicAdd(&sMc[1], e1);
    atomicAdd(&sMc[2], e2);
    atomicAdd(&sMc[3], e3);
    __syncthreads();
    atomicAdd(&((float*)g_M)[tid], sM[tid]);
    if (tid < 2) atomicAdd(&g_cnt[tid], scnt[tid]);
}

// ---------------- K3: int8 MMA sim tiles, upper triangle --------------------
// CTA = 128x128 tile; 8 warps as 2(m) x 4(n); warp tile 64x32; s32 acc.
__global__ void __launch_bounds__(256, 2) k_sim() {
    int idx = blockIdx.x;
    int bj = (int)((sqrtf(8.0f * (float)idx + 1.0f) - 1.0f) * 0.5f);
    while ((bj + 1) * (bj + 2) / 2 <= idx) bj++;
    while (bj * (bj + 1) / 2 > idx) bj--;
    int bi = idx - bj * (bj + 1) / 2;

    __shared__ __align__(16) char smA[128 * 128];
    __shared__ __align__(16) char smB[128 * 128];
    __shared__ float sA[128], sB[128];
    __shared__ float red[128], redc[128];

    uint32_t sbA = smem_u32(smA), sbB = smem_u32(smB);
    int tid = threadIdx.x;
    int wid = tid >> 5, lane = tid & 31;
    int i0 = bi * 128, j0 = bj * 128;
    bool diag = (bi == bj);

    if (tid < 128) {
        red[tid] = 0.0f; redc[tid] = 0.0f;
        sA[tid] = g_s[i0 + tid];
        sB[tid] = g_s[j0 + tid];
    }
    #pragma unroll
    for (int c = 0; c < 4; c++) {
        int flat = c * 256 + tid;
        int row = flat >> 3, ch = flat & 7;
        uint32_t off = (uint32_t)(row * 128 + ((ch ^ (row & 7)) << 4));
        *(uint4*)(smA + off) = ((const uint4*)&g_q[(size_t)(i0 + row) * DDIM])[ch];
        *(uint4*)(smB + off) = ((const uint4*)&g_q[(size_t)(j0 + row) * DDIM])[ch];
    }
    __syncthreads();

    int m_off = (wid >> 2) * 64;
    int n_off = (wid & 3) * 32;

    int acc[4][4][4];
    #pragma unroll
    for (int mt = 0; mt < 4; mt++)
        #pragma unroll
        for (int nt = 0; nt < 4; nt++)
            #pragma unroll
            for (int e = 0; e < 4; e++) acc[mt][nt][e] = 0;

    uint32_t rowA = (uint32_t)(m_off + (lane & 15));
    uint32_t chA  = (uint32_t)(lane >> 4);
    uint32_t rowB = (uint32_t)(n_off + (lane & 7) + ((lane >> 4) << 3));
    uint32_t chB  = (uint32_t)((lane >> 3) & 1);

    #pragma unroll
    for (int kk = 0; kk < 4; kk++) {
        uint32_t a[4][4];
        #pragma unroll
        for (int mt = 0; mt < 4; mt++) {
            uint32_t r = rowA + mt * 16;
            uint32_t ch = (uint32_t)(kk * 2) + chA;
            ldsm_x4(sbA + r * 128 + ((ch ^ (r & 7)) << 4),
                    a[mt][0], a[mt][1], a[mt][2], a[mt][3]);
        }
        uint32_t b[4][2];
        #pragma unroll
        for (int p = 0; p < 2; p++) {
            uint32_t r = rowB + (uint32_t)(p * 16);
            uint32_t ch = (uint32_t)(kk * 2) + chB;
            ldsm_x4(sbB + r * 128 + ((ch ^ (r & 7)) << 4),
                    b[2 * p][0], b[2 * p][1], b[2 * p + 1][0], b[2 * p + 1][1]);
        }
        #pragma unroll
        for (int mt = 0; mt < 4; mt++)
            #pragma unroll
            for (int nt = 0; nt < 4; nt++)
                mma16832s8(acc[mt][nt], a[mt][0], a[mt][1], a[mt][2], a[mt][3],
                           b[nt][0], b[nt][1]);
    }

    // ---- epilogue: e = exp2(acc * s_i * s_j), row sums + col sums ----
    int lrow = lane >> 2;
    int lcol = (lane & 3) * 2;
    float2 cs[4];
    #pragma unroll
    for (int nt = 0; nt < 4; nt++)
        cs[nt] = *(float2*)&sB[n_off + nt * 8 + lcol];

    float colacc[4][2];
    #pragma unroll
    for (int nt = 0; nt < 4; nt++) { colacc[nt][0] = 0.0f; colacc[nt][1] = 0.0f; }

    #pragma unroll
    for (int mt = 0; mt < 4; mt++) {
        int grow0 = i0 + m_off + mt * 16 + lrow;
        float rs0 = sA[m_off + mt * 16 + lrow];
        float rs1 = sA[m_off + mt * 16 + lrow + 8];
        float s0 = 0.0f, s1 = 0.0f;
        #pragma unroll
        for (int nt = 0; nt < 4; nt++) {
            int gcol = j0 + n_off + nt * 8 + lcol;
            float e0 = ex2f((float)acc[mt][nt][0] * (rs0 * cs[nt].x));
            float e1 = ex2f((float)acc[mt][nt][1] * (rs0 * cs[nt].y));
            float e2 = ex2f((float)acc[mt][nt][2] * (rs1 * cs[nt].x));
            float e3 = ex2f((float)acc[mt][nt][3] * (rs1 * cs[nt].y));
            if (diag) {
                if (gcol     == grow0)     e0 = 0.0f;
                if (gcol + 1 == grow0)     e1 = 0.0f;
                if (gcol     == grow0 + 8) e2 = 0.0f;
                if (gcol + 1 == grow0 + 8) e3 = 0.0f;
            }
            s0 += e0 + e1;
            s1 += e2 + e3;
            colacc[nt][0] += e0 + e2;
            colacc[nt][1] += e1 + e3;
        }
        s0 += __shfl_xor_sync(0xffffffffu, s0, 1);
        s0 += __shfl_xor_sync(0xffffffffu, s0, 2);
        s1 += __shfl_xor_sync(0xffffffffu, s1, 1);
        s1 += __shfl_xor_sync(0xffffffffu, s1, 2);
        if ((lane & 3) == 0) {
            atomicAdd(&red[m_off + mt * 16 + lrow], s0);
            atomicAdd(&red[m_off + mt * 16 + lrow + 8], s1);
        }
    }

    if (!diag) {
        #pragma unroll
        for (int nt = 0; nt < 4; nt++) {
            #pragma unroll
            for (int h = 0; h < 2; h++) {
                float c = colacc[nt][h];
                c += __shfl_xor_sync(0xffffffffu, c, 4);
                c += __shfl_xor_sync(0xffffffffu, c, 8);
                c += __shfl_xor_sync(0xffffffffu, c, 16);
                if (lane < 4)
                    atomicAdd(&redc[n_off + nt * 8 + (lane & 3) * 2 + h], c);
            }
        }
    }

    __syncthreads();
    if (tid < 128) {
        atomicAdd(&g_denom[i0 + tid], red[tid]);
        if (!diag) atomicAdd(&g_denom[j0 + tid], redc[tid]);
    }
}

// ---------------- K4: gated log-sums + closed-form final --------------------
// loss = [-|M0|^2 + n0 + (n0-1)*L0]/n0 + [-|M1|^2 + n1 + (n1-1)*L1]
// where Lc = sum_{i in class c} log(denom_i).  (pos terms telescope to |Mc|^2)
__global__ void k_loss(const int* __restrict__ l32, float* __restrict__ out) {
    int i = blockIdx.x * 256 + threadIdx.x;
    int t = threadIdx.x;
    int c = (get_label(l32, i) == 0) ? 0 : 1;
    float li = logf(g_denom[i]);

    __shared__ float sh0[256], sh1[256];
    sh0[t] = (c == 0) ? li : 0.0f;
    sh1[t] = (c == 0) ? 0.0f : li;
    __syncthreads();
    for (int st = 128; st; st >>= 1) {
        if (t < st) { sh0[t] += sh0[t + st]; sh1[t] += sh1[t + st]; }
        __syncthreads();
    }
    __shared__ int ticket;
    if (t == 0) {
        atomicAdd(&g_L[0], sh0[0]);
        atomicAdd(&g_L[1], sh1[0]);
        __threadfence();
        ticket = atomicAdd(&g_done, 1);
    }
    __syncthreads();
    if (ticket == gridDim.x - 1) {
        // final block: |M0|^2, |M1|^2 and the closed form
        float v = ((float*)g_M)[t];         // t<128 -> M0, t>=128 -> M1
        sh0[t] = (t < 128) ? v * v : 0.0f;
        sh1[t] = (t < 128) ? 0.0f : v * v;
        __syncthreads();
        for (int st = 128; st; st >>= 1) {
            if (t < st) { sh0[t] += sh0[t + st]; sh1[t] += sh1[t + st]; }
            __syncthreads();
        }
        if (t == 0) {
            float n0 = (float)g_cnt[0], n1 = (float)g_cnt[1];
            float loss0 = -sh0[0] + n0 + (n0 - 1.0f) * g_L[0];
            float loss1 = -sh1[0] + n1 + (n1 - 1.0f) * g_L[1];
            out[0] = loss0 / n0 + loss1;
        }
    }
}

// ---------------- launch -----------------------------------------------------
extern "C" void kernel_launch(void* const* d_in, const int* in_sizes, int n_in,
                              void* d_out, int out_size) {
    const float* emb = (const float*)d_in[0];
    const int*   l32 = (const int*)d_in[1];
    float*       out = (float*)d_out;

    k_init<<<33, 256>>>(l32);
    k_normalize<<<NROWS / 8, 256>>>(emb, l32);
    k_sim<<<NTRI, 256>>>();
    k_loss<<<NROWS / 256, 256>>>(l32, out);
}

// round 9
// speedup vs baseline: 1.0947x; 1.0026x over previous
#include <cuda_runtime.h>
#include <math.h>
#include <cstdint>

#define NROWS 8192
#define DDIM  128
#define NTILE (NROWS / 128)
#define NTRI  (NTILE * (NTILE + 1) / 2)   // 2080

// ---------------- scratch ----------------------------------------------------
__device__ char  g_q[NROWS * DDIM];       // int8 quantized normalized rows [i][d]
__device__ float g_s[NROWS];              // per-row scale * sqrt(log2e)
__device__ float g_denom[NROWS];
__device__ float g_M[2][DDIM];            // per-class sums of normalized rows
__device__ int   g_cnt[2];
__device__ int   g_lblstride;
__device__ int   g_done;

// ---------------- helpers ----------------------------------------------------
__device__ __forceinline__ uint32_t smem_u32(const void* p) {
    uint32_t a;
    asm("{ .reg .u64 t; cvta.to.shared.u64 t, %1; cvt.u32.u64 %0, t; }" : "=r"(a) : "l"(p));
    return a;
}
__device__ __forceinline__ float ex2f(float x) {
    float r;
    asm("ex2.approx.ftz.f32 %0, %1;" : "=f"(r) : "f"(x));
    return r;
}
__device__ __forceinline__ void ldsm_x4(uint32_t a, uint32_t& r0, uint32_t& r1,
                                        uint32_t& r2, uint32_t& r3) {
    asm volatile("ldmatrix.sync.aligned.m8n8.x4.shared.b16 {%0,%1,%2,%3}, [%4];"
                 : "=r"(r0), "=r"(r1), "=r"(r2), "=r"(r3) : "r"(a));
}
__device__ __forceinline__ void mma16832s8(int* c, uint32_t a0, uint32_t a1,
                                           uint32_t a2, uint32_t a3,
                                           uint32_t b0, uint32_t b1) {
    asm volatile(
        "mma.sync.aligned.m16n8k32.row.col.s32.s8.s8.s32 "
        "{%0,%1,%2,%3}, {%4,%5,%6,%7}, {%8,%9}, {%0,%1,%2,%3};"
        : "+r"(c[0]), "+r"(c[1]), "+r"(c[2]), "+r"(c[3])
        : "r"(a0), "r"(a1), "r"(a2), "r"(a3), "r"(b0), "r"(b1));
}
__device__ __forceinline__ int get_label(const int* l32, int i) { return l32[i * g_lblstride]; }

// ---------------- K_init: zero + label-dtype sniff --------------------------
__global__ void k_init(const int* __restrict__ l32) {
    if (blockIdx.x < 32) {
        int t = blockIdx.x * 256 + threadIdx.x;
        if (t < NROWS) g_denom[t] = 0.0f;
        if (t < 2 * DDIM) ((float*)g_M)[t] = 0.0f;
        if (t < 2) g_cnt[t] = 0;
        if (t == 0) g_done = 0;
    } else {
        int t = threadIdx.x, nz = 0;
        for (int i = t; i < NROWS / 2; i += 256) nz |= l32[2 * i + 1];
        __shared__ int s;
        if (t == 0) s = 0;
        __syncthreads();
        if (nz) atomicOr(&s, 1);
        __syncthreads();
        if (t == 0) g_lblstride = s ? 1 : 2;
    }
}

// ---------------- K1: normalize + int8 quantize + fused class sums ---------
__global__ void k_normalize(const float* __restrict__ emb, const int* __restrict__ l32) {
    const float SQRT_LOG2E = 1.2011224087864498f;
    int tid = threadIdx.x;
    int warp = tid >> 5, lane = tid & 31;
    int row = blockIdx.x * 8 + warp;

    __shared__ float sM[2 * DDIM];
    __shared__ int   scnt[2];
    sM[tid] = 0.0f;
    if (tid < 2) scnt[tid] = 0;
    __syncthreads();

    float4 v = ((const float4*)(emb + (size_t)row * DDIM))[lane];
    float ss = v.x * v.x + v.y * v.y + v.z * v.z + v.w * v.w;
    float mx = fmaxf(fmaxf(fabsf(v.x), fabsf(v.y)), fmaxf(fabsf(v.z), fabsf(v.w)));
    #pragma unroll
    for (int o = 16; o; o >>= 1) {
        ss += __shfl_xor_sync(0xffffffffu, ss, o);
        mx = fmaxf(mx, __shfl_xor_sync(0xffffffffu, mx, o));
    }
    float r = rsqrtf(ss);
    float m = mx * r;
    float qs = 127.0f / m;
    int d = lane * 4;
    float e0 = v.x * r, e1 = v.y * r, e2 = v.z * r, e3 = v.w * r;
    char4 q = make_char4((char)__float2int_rn(e0 * qs), (char)__float2int_rn(e1 * qs),
                         (char)__float2int_rn(e2 * qs), (char)__float2int_rn(e3 * qs));
    *(char4*)&g_q[(size_t)row * DDIM + d] = q;
    int c = (get_label(l32, row) == 0) ? 0 : 1;
    if (lane == 0) {
        g_s[row] = (m / 127.0f) * SQRT_LOG2E;
        atomicAdd(&scnt[c], 1);
    }
    float* sMc = &sM[c * DDIM + d];
    atomicAdd(&sMc[0], e0);
    atomicAdd(&sMc[1], e1);
    atomicAdd(&sMc[2], e2);
    atomicAdd(&sMc[3], e3);
    __syncthreads();
    atomicAdd(&((float*)g_M)[tid], sM[tid]);
    if (tid < 2) atomicAdd(&g_cnt[tid], scnt[tid]);
}

// ---------------- K3: int8 MMA sim tiles + fused loss tail -------------------
// CTA = 128x128 tile; 8 warps as 2(m) x 4(n); warp tile 64x32; s32 acc.
// The LAST CTA (g_done ticket) computes the closed-form loss:
//   loss = [-|M0|^2 + n0 + (n0-1)*L0]/n0 + [-|M1|^2 + n1 + (n1-1)*L1],
//   Lc = sum_{i in class c} log(denom_i)
__global__ void __launch_bounds__(256, 2) k_sim(const int* __restrict__ l32,
                                                float* __restrict__ out) {
    int idx = blockIdx.x;
    int bj = (int)((sqrtf(8.0f * (float)idx + 1.0f) - 1.0f) * 0.5f);
    while ((bj + 1) * (bj + 2) / 2 <= idx) bj++;
    while (bj * (bj + 1) / 2 > idx) bj--;
    int bi = idx - bj * (bj + 1) / 2;

    __shared__ __align__(16) char smA[128 * 128];
    __shared__ __align__(16) char smB[128 * 128];
    __shared__ float sA[128], sB[128];
    __shared__ float red[128], redc[128];

    uint32_t sbA = smem_u32(smA), sbB = smem_u32(smB);
    int tid = threadIdx.x;
    int wid = tid >> 5, lane = tid & 31;
    int i0 = bi * 128, j0 = bj * 128;
    bool diag = (bi == bj);

    if (tid < 128) {
        red[tid] = 0.0f; redc[tid] = 0.0f;
        sA[tid] = g_s[i0 + tid];
        sB[tid] = g_s[j0 + tid];
    }
    #pragma unroll
    for (int c = 0; c < 4; c++) {
        int flat = c * 256 + tid;
        int row = flat >> 3, ch = flat & 7;
        uint32_t off = (uint32_t)(row * 128 + ((ch ^ (row & 7)) << 4));
        *(uint4*)(smA + off) = ((const uint4*)&g_q[(size_t)(i0 + row) * DDIM])[ch];
        *(uint4*)(smB + off) = ((const uint4*)&g_q[(size_t)(j0 + row) * DDIM])[ch];
    }
    __syncthreads();

    int m_off = (wid >> 2) * 64;
    int n_off = (wid & 3) * 32;

    int acc[4][4][4];
    #pragma unroll
    for (int mt = 0; mt < 4; mt++)
        #pragma unroll
        for (int nt = 0; nt < 4; nt++)
            #pragma unroll
            for (int e = 0; e < 4; e++) acc[mt][nt][e] = 0;

    uint32_t rowA = (uint32_t)(m_off + (lane & 15));
    uint32_t chA  = (uint32_t)(lane >> 4);
    uint32_t rowB = (uint32_t)(n_off + (lane & 7) + ((lane >> 4) << 3));
    uint32_t chB  = (uint32_t)((lane >> 3) & 1);

    #pragma unroll
    for (int kk = 0; kk < 4; kk++) {
        uint32_t a[4][4];
        #pragma unroll
        for (int mt = 0; mt < 4; mt++) {
            uint32_t r = rowA + mt * 16;
            uint32_t ch = (uint32_t)(kk * 2) + chA;
            ldsm_x4(sbA + r * 128 + ((ch ^ (r & 7)) << 4),
                    a[mt][0], a[mt][1], a[mt][2], a[mt][3]);
        }
        uint32_t b[4][2];
        #pragma unroll
        for (int p = 0; p < 2; p++) {
            uint32_t r = rowB + (uint32_t)(p * 16);
            uint32_t ch = (uint32_t)(kk * 2) + chB;
            ldsm_x4(sbB + r * 128 + ((ch ^ (r & 7)) << 4),
                    b[2 * p][0], b[2 * p][1], b[2 * p + 1][0], b[2 * p + 1][1]);
        }
        #pragma unroll
        for (int mt = 0; mt < 4; mt++)
            #pragma unroll
            for (int nt = 0; nt < 4; nt++)
                mma16832s8(acc[mt][nt], a[mt][0], a[mt][1], a[mt][2], a[mt][3],
                           b[nt][0], b[nt][1]);
    }

    // ---- epilogue: e = exp2(acc * s_i * s_j), row sums + col sums ----
    int lrow = lane >> 2;
    int lcol = (lane & 3) * 2;
    float2 cs[4];
    #pragma unroll
    for (int nt = 0; nt < 4; nt++)
        cs[nt] = *(float2*)&sB[n_off + nt * 8 + lcol];

    float colacc[4][2];
    #pragma unroll
    for (int nt = 0; nt < 4; nt++) { colacc[nt][0] = 0.0f; colacc[nt][1] = 0.0f; }

    #pragma unroll
    for (int mt = 0; mt < 4; mt++) {
        int grow0 = i0 + m_off + mt * 16 + lrow;
        float rs0 = sA[m_off + mt * 16 + lrow];
        float rs1 = sA[m_off + mt * 16 + lrow + 8];
        float s0 = 0.0f, s1 = 0.0f;
        #pragma unroll
        for (int nt = 0; nt < 4; nt++) {
            int gcol = j0 + n_off + nt * 8 + lcol;
            float e0 = ex2f((float)acc[mt][nt][0] * (rs0 * cs[nt].x));
            float e1 = ex2f((float)acc[mt][nt][1] * (rs0 * cs[nt].y));
            float e2 = ex2f((float)acc[mt][nt][2] * (rs1 * cs[nt].x));
            float e3 = ex2f((float)acc[mt][nt][3] * (rs1 * cs[nt].y));
            if (diag) {
                if (gcol     == grow0)     e0 = 0.0f;
                if (gcol + 1 == grow0)     e1 = 0.0f;
                if (gcol     == grow0 + 8) e2 = 0.0f;
                if (gcol + 1 == grow0 + 8) e3 = 0.0f;
            }
            s0 += e0 + e1;
            s1 += e2 + e3;
            colacc[nt][0] += e0 + e2;
            colacc[nt][1] += e1 + e3;
        }
        s0 += __shfl_xor_sync(0xffffffffu, s0, 1);
        s0 += __shfl_xor_sync(0xffffffffu, s0, 2);
        s1 += __shfl_xor_sync(0xffffffffu, s1, 1);
        s1 += __shfl_xor_sync(0xffffffffu, s1, 2);
        if ((lane & 3) == 0) {
            atomicAdd(&red[m_off + mt * 16 + lrow], s0);
            atomicAdd(&red[m_off + mt * 16 + lrow + 8], s1);
        }
    }

    if (!diag) {
        #pragma unroll
        for (int nt = 0; nt < 4; nt++) {
            #pragma unroll
            for (int h = 0; h < 2; h++) {
                float c = colacc[nt][h];
                c += __shfl_xor_sync(0xffffffffu, c, 4);
                c += __shfl_xor_sync(0xffffffffu, c, 8);
                c += __shfl_xor_sync(0xffffffffu, c, 16);
                if (lane < 4)
                    atomicAdd(&redc[n_off + nt * 8 + (lane & 3) * 2 + h], c);
            }
        }
    }

    __syncthreads();
    if (tid < 128) {
        atomicAdd(&g_denom[i0 + tid], red[tid]);
        if (!diag) atomicAdd(&g_denom[j0 + tid], redc[tid]);
    }

    // ---- ticket: last CTA computes the loss ----
    __shared__ int ticket;
    if (tid == 0) {
        __threadfence();
        ticket = atomicAdd(&g_done, 1);
    }
    __syncthreads();
    if (ticket != NTRI - 1) return;

    // last CTA: gated log sums over all denoms (coalesced), then |Mc|^2
    float l0 = 0.0f, l1 = 0.0f;
    #pragma unroll 4
    for (int ch = 0; ch < NROWS / 256; ch++) {
        int i = ch * 256 + tid;
        float li = logf(g_denom[i]);
        if (get_label(l32, i) == 0) l0 += li; else l1 += li;
    }
    // reuse red/redc as reduction buffers (256 floats each)
    float* sh0 = red;    // NOTE: red is 128 floats; need 256 -> use sA/sB too
    // simpler: warp-reduce then smem of 8 partials
    #pragma unroll
    for (int o = 16; o; o >>= 1) {
        l0 += __shfl_xor_sync(0xffffffffu, l0, o);
        l1 += __shfl_xor_sync(0xffffffffu, l1, o);
    }
    __shared__ float w0[8], w1[8];
    if (lane == 0) { w0[wid] = l0; w1[wid] = l1; }

    // |Mc|^2: 256 threads over 2*128 entries of g_M
    float v = ((float*)g_M)[tid];
    float q0 = (tid < 128) ? v * v : 0.0f;
    float q1 = (tid < 128) ? 0.0f : v * v;
    #pragma unroll
    for (int o = 16; o; o >>= 1) {
        q0 += __shfl_xor_sync(0xffffffffu, q0, o);
        q1 += __shfl_xor_sync(0xffffffffu, q1, o);
    }
    __shared__ float m0[8], m1[8];
    if (lane == 0) { m0[wid] = q0; m1[wid] = q1; }
    __syncthreads();

    if (tid == 0) {
        float L0 = 0.0f, L1 = 0.0f, M0 = 0.0f, M1 = 0.0f;
        #pragma unroll
        for (int w = 0; w < 8; w++) {
            L0 += w0[w]; L1 += w1[w];
            M0 += m0[w]; M1 += m1[w];
        }
        float n0 = (float)g_cnt[0], n1 = (float)g_cnt[1];
        float loss0 = -M0 + n0 + (n0 - 1.0f) * L0;
        float loss1 = -M1 + n1 + (n1 - 1.0f) * L1;
        out[0] = loss0 / n0 + loss1;
    }
    (void)sh0;
}

// ---------------- launch -----------------------------------------------------
extern "C" void kernel_launch(void* const* d_in, const int* in_sizes, int n_in,
                              void* d_out, int out_size) {
    const float* emb = (const float*)d_in[0];
    const int*   l32 = (const int*)d_in[1];
    float*       out = (float*)d_out;

    k_init<<<33, 256>>>(l32);
    k_normalize<<<NROWS / 8, 256>>>(emb, l32);
    k_sim<<<NTRI, 256>>>(l32, out);
}

// round 10
// speedup vs baseline: 1.1355x; 1.0372x over previous
#include <cuda_runtime.h>
#include <math.h>
#include <cstdint>

#define NROWS 8192
#define DDIM  128
#define NTILE (NROWS / 128)               // 64 slabs of 128 rows
#define NTRI  (NTILE * (NTILE + 1) / 2)   // 2080 tiles
#define NBLK  128                         // k_normalize blocks (64 rows each)

// ---------------- scratch (all init-free or self-resetting) -----------------
__device__ char  g_q[NROWS * DDIM];       // int8 quantized normalized rows
__device__ float g_s[NROWS];              // per-row scale * sqrt(log2e)
__device__ float g_denom[NROWS];          // zeroed by k_normalize each run
__device__ float g_Mpart[NBLK][2 * DDIM]; // per-block class-sum partials
__device__ int   g_cntpart[NBLK][2];      // per-block class counts
__device__ float g_Lpart[NTILE][2];       // per-slab gated log sums
__device__ int   g_slabcnt[NTILE];        // 0 at start; reset by finisher
__device__ int   g_slabs;                 // 0 at start; reset by final finisher
__device__ int   g_lblstride;

// ---------------- helpers ----------------------------------------------------
__device__ __forceinline__ uint32_t smem_u32(const void* p) {
    uint32_t a;
    asm("{ .reg .u64 t; cvta.to.shared.u64 t, %1; cvt.u32.u64 %0, t; }" : "=r"(a) : "l"(p));
    return a;
}
__device__ __forceinline__ float ex2f(float x) {
    float r;
    asm("ex2.approx.ftz.f32 %0, %1;" : "=f"(r) : "f"(x));
    return r;
}
__device__ __forceinline__ void ldsm_x4(uint32_t a, uint32_t& r0, uint32_t& r1,
                                        uint32_t& r2, uint32_t& r3) {
    asm volatile("ldmatrix.sync.aligned.m8n8.x4.shared.b16 {%0,%1,%2,%3}, [%4];"
                 : "=r"(r0), "=r"(r1), "=r"(r2), "=r"(r3) : "r"(a));
}
__device__ __forceinline__ void mma16832s8(int* c, uint32_t a0, uint32_t a1,
                                           uint32_t a2, uint32_t a3,
                                           uint32_t b0, uint32_t b1) {
    asm volatile(
        "mma.sync.aligned.m16n8k32.row.col.s32.s8.s8.s32 "
        "{%0,%1,%2,%3}, {%4,%5,%6,%7}, {%8,%9}, {%0,%1,%2,%3};"
        : "+r"(c[0]), "+r"(c[1]), "+r"(c[2]), "+r"(c[3])
        : "r"(a0), "r"(a1), "r"(a2), "r"(a3), "r"(b0), "r"(b1));
}
__device__ __forceinline__ int get_label(const int* l32, int i) { return l32[i * g_lblstride]; }

// ---------------- K1: normalize + quantize + partial class sums -------------
// 128 blocks x 256 threads; block b owns rows [64b, 64b+64).
// Also: label-dtype sniff (first 256 odd words), g_denom zeroing,
// per-block partials written non-atomically (no init kernel needed).
__global__ void __launch_bounds__(256) k_normalize(const float* __restrict__ emb,
                                                   const int* __restrict__ l32) {
    const float SQRT_LOG2E = 1.2011224087864498f;
    int tid = threadIdx.x;
    int wid = tid >> 5, lane = tid & 31;
    int b = blockIdx.x;

    // label dtype sniff: labels are 0/1; int64 LE => odd int32 words are 0.
    __shared__ int sdet;
    __shared__ float sM[2 * DDIM];
    __shared__ int   scnt[2];
    if (tid == 0) sdet = 0;
    sM[tid] = 0.0f;
    if (tid < 2) scnt[tid] = 0;
    __syncthreads();
    if (l32[2 * tid + 1] != 0) atomicOr(&sdet, 1);   // reads ints [1..511]: safe either dtype
    __syncthreads();
    int stride = sdet ? 1 : 2;
    if (tid == 0 && b == 0) g_lblstride = stride;

    // zero this block's slice of g_denom (64 entries)
    if (tid < 64) g_denom[b * 64 + tid] = 0.0f;

    // 8 rows per warp
    #pragma unroll
    for (int it = 0; it < 8; it++) {
        int row = b * 64 + wid * 8 + it;
        float4 v = ((const float4*)(emb + (size_t)row * DDIM))[lane];
        float ss = v.x * v.x + v.y * v.y + v.z * v.z + v.w * v.w;
        float mx = fmaxf(fmaxf(fabsf(v.x), fabsf(v.y)), fmaxf(fabsf(v.z), fabsf(v.w)));
        #pragma unroll
        for (int o = 16; o; o >>= 1) {
            ss += __shfl_xor_sync(0xffffffffu, ss, o);
            mx = fmaxf(mx, __shfl_xor_sync(0xffffffffu, mx, o));
        }
        float r = rsqrtf(ss);
        float m = mx * r;
        float qs = 127.0f / m;
        int d = lane * 4;
        float e0 = v.x * r, e1 = v.y * r, e2 = v.z * r, e3 = v.w * r;
        char4 q = make_char4((char)__float2int_rn(e0 * qs), (char)__float2int_rn(e1 * qs),
                             (char)__float2int_rn(e2 * qs), (char)__float2int_rn(e3 * qs));
        *(char4*)&g_q[(size_t)row * DDIM + d] = q;
        int c = (l32[row * stride] == 0) ? 0 : 1;
        if (lane == 0) {
            g_s[row] = (m / 127.0f) * SQRT_LOG2E;
            atomicAdd(&scnt[c], 1);
        }
        float* sMc = &sM[c * DDIM + d];
        atomicAdd(&sMc[0], e0);
        atomicAdd(&sMc[1], e1);
        atomicAdd(&sMc[2], e2);
        atomicAdd(&sMc[3], e3);
    }
    __syncthreads();
    g_Mpart[b][tid] = sM[tid];
    if (tid < 2) g_cntpart[b][tid] = scnt[tid];
}

// ---------------- K2: int8 MMA sim tiles + distributed loss tails -----------
// CTA = 128x128 tile; 8 warps as 2(m) x 4(n); warp tile 64x32; s32 acc.
// Slab s (128 rows of g_denom) is complete after 64 CTA contributions;
// the 64th contributor computes that slab's gated log sums. The CTA that
// completes the 64th slab assembles the closed-form loss:
//   loss = [-|M0|^2 + n0 + (n0-1)*L0]/n0 + [-|M1|^2 + n1 + (n1-1)*L1]
__global__ void __launch_bounds__(256, 2) k_sim(const int* __restrict__ l32,
                                                float* __restrict__ out) {
    int idx = blockIdx.x;
    int bj = (int)((sqrtf(8.0f * (float)idx + 1.0f) - 1.0f) * 0.5f);
    while ((bj + 1) * (bj + 2) / 2 <= idx) bj++;
    while (bj * (bj + 1) / 2 > idx) bj--;
    int bi = idx - bj * (bj + 1) / 2;

    __shared__ __align__(16) char smA[128 * 128];
    __shared__ __align__(16) char smB[128 * 128];
    __shared__ float sA[128], sB[128];
    __shared__ float red[128], redc[128];

    uint32_t sbA = smem_u32(smA), sbB = smem_u32(smB);
    int tid = threadIdx.x;
    int wid = tid >> 5, lane = tid & 31;
    int i0 = bi * 128, j0 = bj * 128;
    bool diag = (bi == bj);

    if (tid < 128) {
        red[tid] = 0.0f; redc[tid] = 0.0f;
        sA[tid] = g_s[i0 + tid];
        sB[tid] = g_s[j0 + tid];
    }
    #pragma unroll
    for (int c = 0; c < 4; c++) {
        int flat = c * 256 + tid;
        int row = flat >> 3, ch = flat & 7;
        uint32_t off = (uint32_t)(row * 128 + ((ch ^ (row & 7)) << 4));
        *(uint4*)(smA + off) = ((const uint4*)&g_q[(size_t)(i0 + row) * DDIM])[ch];
        *(uint4*)(smB + off) = ((const uint4*)&g_q[(size_t)(j0 + row) * DDIM])[ch];
    }
    __syncthreads();

    int m_off = (wid >> 2) * 64;
    int n_off = (wid & 3) * 32;

    int acc[4][4][4];
    #pragma unroll
    for (int mt = 0; mt < 4; mt++)
        #pragma unroll
        for (int nt = 0; nt < 4; nt++)
            #pragma unroll
            for (int e = 0; e < 4; e++) acc[mt][nt][e] = 0;

    uint32_t rowA = (uint32_t)(m_off + (lane & 15));
    uint32_t chA  = (uint32_t)(lane >> 4);
    uint32_t rowB = (uint32_t)(n_off + (lane & 7) + ((lane >> 4) << 3));
    uint32_t chB  = (uint32_t)((lane >> 3) & 1);

    #pragma unroll
    for (int kk = 0; kk < 4; kk++) {
        uint32_t a[4][4];
        #pragma unroll
        for (int mt = 0; mt < 4; mt++) {
            uint32_t r = rowA + mt * 16;
            uint32_t ch = (uint32_t)(kk * 2) + chA;
            ldsm_x4(sbA + r * 128 + ((ch ^ (r & 7)) << 4),
                    a[mt][0], a[mt][1], a[mt][2], a[mt][3]);
        }
        uint32_t b[4][2];
        #pragma unroll
        for (int p = 0; p < 2; p++) {
            uint32_t r = rowB + (uint32_t)(p * 16);
            uint32_t ch = (uint32_t)(kk * 2) + chB;
            ldsm_x4(sbB + r * 128 + ((ch ^ (r & 7)) << 4),
                    b[2 * p][0], b[2 * p][1], b[2 * p + 1][0], b[2 * p + 1][1]);
        }
        #pragma unroll
        for (int mt = 0; mt < 4; mt++)
            #pragma unroll
            for (int nt = 0; nt < 4; nt++)
                mma16832s8(acc[mt][nt], a[mt][0], a[mt][1], a[mt][2], a[mt][3],
                           b[nt][0], b[nt][1]);
    }

    // ---- epilogue: e = exp2(acc * s_i * s_j), row sums + col sums ----
    int lrow = lane >> 2;
    int lcol = (lane & 3) * 2;
    float2 cs[4];
    #pragma unroll
    for (int nt = 0; nt < 4; nt++)
        cs[nt] = *(float2*)&sB[n_off + nt * 8 + lcol];

    float colacc[4][2];
    #pragma unroll
    for (int nt = 0; nt < 4; nt++) { colacc[nt][0] = 0.0f; colacc[nt][1] = 0.0f; }

    #pragma unroll
    for (int mt = 0; mt < 4; mt++) {
        int grow0 = i0 + m_off + mt * 16 + lrow;
        float rs0 = sA[m_off + mt * 16 + lrow];
        float rs1 = sA[m_off + mt * 16 + lrow + 8];
        float s0 = 0.0f, s1 = 0.0f;
        #pragma unroll
        for (int nt = 0; nt < 4; nt++) {
            int gcol = j0 + n_off + nt * 8 + lcol;
            float e0 = ex2f((float)acc[mt][nt][0] * (rs0 * cs[nt].x));
            float e1 = ex2f((float)acc[mt][nt][1] * (rs0 * cs[nt].y));
            float e2 = ex2f((float)acc[mt][nt][2] * (rs1 * cs[nt].x));
            float e3 = ex2f((float)acc[mt][nt][3] * (rs1 * cs[nt].y));
            if (diag) {
                if (gcol     == grow0)     e0 = 0.0f;
                if (gcol + 1 == grow0)     e1 = 0.0f;
                if (gcol     == grow0 + 8) e2 = 0.0f;
                if (gcol + 1 == grow0 + 8) e3 = 0.0f;
            }
            s0 += e0 + e1;
            s1 += e2 + e3;
            colacc[nt][0] += e0 + e2;
            colacc[nt][1] += e1 + e3;
        }
        s0 += __shfl_xor_sync(0xffffffffu, s0, 1);
        s0 += __shfl_xor_sync(0xffffffffu, s0, 2);
        s1 += __shfl_xor_sync(0xffffffffu, s1, 1);
        s1 += __shfl_xor_sync(0xffffffffu, s1, 2);
        if ((lane & 3) == 0) {
            atomicAdd(&red[m_off + mt * 16 + lrow], s0);
            atomicAdd(&red[m_off + mt * 16 + lrow + 8], s1);
        }
    }

    if (!diag) {
        #pragma unroll
        for (int nt = 0; nt < 4; nt++) {
            #pragma unroll
            for (int h = 0; h < 2; h++) {
                float c = colacc[nt][h];
                c += __shfl_xor_sync(0xffffffffu, c, 4);
                c += __shfl_xor_sync(0xffffffffu, c, 8);
                c += __shfl_xor_sync(0xffffffffu, c, 16);
                if (lane < 4)
                    atomicAdd(&redc[n_off + nt * 8 + (lane & 3) * 2 + h], c);
            }
        }
    }

    __syncthreads();
    if (tid < 128) {
        atomicAdd(&g_denom[i0 + tid], red[tid]);
        if (!diag) atomicAdd(&g_denom[j0 + tid], redc[tid]);
    }

    // ---- slab tickets: 64th contributor processes the slab's logs ----
    __shared__ int fin_i, fin_j;
    __shared__ float wred[8];
    if (tid == 0) {
        __threadfence();
        fin_i = (atomicAdd(&g_slabcnt[bi], 1) == 63) ? 1 : 0;
        fin_j = (!diag && atomicAdd(&g_slabcnt[bj], 1) == 63) ? 1 : 0;
    }
    __syncthreads();
    int nfin = fin_i + fin_j;
    if (nfin == 0) return;

    __threadfence();   // acquire: all 64 contributions' denom atomics visible
    #pragma unroll
    for (int which = 0; which < 2; which++) {
        int doit = which == 0 ? fin_i : fin_j;
        int s    = which == 0 ? bi : bj;
        if (!doit) continue;
        float l0 = 0.0f, l1 = 0.0f;
        if (tid < 128) {
            int row = s * 128 + tid;
            float li = logf(g_denom[row]);
            if (get_label(l32, row) == 0) l0 = li; else l1 = li;
        }
        #pragma unroll
        for (int o = 16; o; o >>= 1) {
            l0 += __shfl_xor_sync(0xffffffffu, l0, o);
            l1 += __shfl_xor_sync(0xffffffffu, l1, o);
        }
        if (lane == 0 && wid < 4) { wred[wid] = l0; wred[wid + 4] = l1; }
        __syncthreads();
        if (tid == 0) {
            g_Lpart[s][0] = wred[0] + wred[1] + wred[2] + wred[3];
            g_Lpart[s][1] = wred[4] + wred[5] + wred[6] + wred[7];
            g_slabcnt[s] = 0;                      // self-reset for next replay
        }
        __syncthreads();
    }

    // ---- final ticket: assemble the loss ----
    __shared__ int final_fin;
    if (tid == 0) {
        __threadfence();
        int old = atomicAdd(&g_slabs, nfin);
        final_fin = (old + nfin == NTILE) ? 1 : 0;
        if (final_fin) g_slabs = 0;                // self-reset
    }
    __syncthreads();
    if (!final_fin) return;
    __threadfence();

    // M[d] summed over blocks (coalesced per iteration), then |Mc|^2
    float Md = 0.0f;
    #pragma unroll 8
    for (int b = 0; b < NBLK; b++) Md += g_Mpart[b][tid];
    float q0 = (tid < 128) ? Md * Md : 0.0f;
    float q1 = (tid < 128) ? 0.0f : Md * Md;
    #pragma unroll
    for (int o = 16; o; o >>= 1) {
        q0 += __shfl_xor_sync(0xffffffffu, q0, o);
        q1 += __shfl_xor_sync(0xffffffffu, q1, o);
    }
    __shared__ float sm0[8], sm1[8];
    if (lane == 0) { sm0[wid] = q0; sm1[wid] = q1; }

    // counts + L partials: threads 0..127 cover NBLK / NTILE entries
    float L0 = 0.0f, L1 = 0.0f;
    int   c0 = 0,   c1 = 0;
    if (tid < NTILE) { L0 = g_Lpart[tid][0]; L1 = g_Lpart[tid][1]; }
    if (tid < NBLK)  { c0 = g_cntpart[tid][0]; c1 = g_cntpart[tid][1]; }
    #pragma unroll
    for (int o = 16; o; o >>= 1) {
        L0 += __shfl_xor_sync(0xffffffffu, L0, o);
        L1 += __shfl_xor_sync(0xffffffffu, L1, o);
        c0 += __shfl_xor_sync(0xffffffffu, c0, o);
        c1 += __shfl_xor_sync(0xffffffffu, c1, o);
    }
    __shared__ float sL0[8], sL1[8];
    __shared__ int   sc0[8], sc1[8];
    if (lane == 0) { sL0[wid] = L0; sL1[wid] = L1; sc0[wid] = c0; sc1[wid] = c1; }
    __syncthreads();

    if (tid == 0) {
        float M0 = 0.0f, M1 = 0.0f, TL0 = 0.0f, TL1 = 0.0f;
        int   n0i = 0, n1i = 0;
        #pragma unroll
        for (int w = 0; w < 8; w++) {
            M0 += sm0[w]; M1 += sm1[w];
            TL0 += sL0[w]; TL1 += sL1[w];
            n0i += sc0[w]; n1i += sc1[w];
        }
        float n0 = (float)n0i, n1 = (float)n1i;
        float loss0 = -M0 + n0 + (n0 - 1.0f) * TL0;
        float loss1 = -M1 + n1 + (n1 - 1.0f) * TL1;
        out[0] = loss0 / n0 + loss1;
    }
}

// ---------------- launch -----------------------------------------------------
extern "C" void kernel_launch(void* const* d_in, const int* in_sizes, int n_in,
                              void* d_out, int out_size) {
    const float* emb = (const float*)d_in[0];
    const int*   l32 = (const int*)d_in[1];
    float*       out = (float*)d_out;

    k_normalize<<<NBLK, 256>>>(emb, l32);
    k_sim<<<NTRI, 256>>>(l32, out);
}